// round 1
// baseline (speedup 1.0000x reference)
#include <cuda_runtime.h>
#include <math.h>

#define EPS 1e-8f
#define LN_EPS 1e-5f
#define CHUNK 32

// ---------------- scratch (static __device__, no allocs) ----------------
__device__ float  g_q[16*512*64];
__device__ float  g_z[16*512*64];
__device__ float  g_v[16*512*64];
__device__ float  g_rqn[16*512];
__device__ float  g_part[16*16*4160];
__device__ float  g_base[16*16*4160];
__device__ float4 g_pack[16*4096];      // {sg, sb+Ps_ln, ng, nb+Mprev_ln}
__device__ float  g_Pz[16*64];          // P_z_ln last step per batch
__device__ double g_acc[2];             // sum, sumsq for std

__device__ __forceinline__ float eluf(float x){ return x > 0.f ? x : (expf(x) - 1.f); }

// block of 256 threads (8 warps). red: >= 8*N floats smem, out: >= N floats smem
template<int N>
__device__ __forceinline__ void block_reduce(float* v, float* red, float* out){
    int lane = threadIdx.x & 31, w = threadIdx.x >> 5;
    #pragma unroll
    for (int i = 0; i < N; i++){
        float x = v[i];
        #pragma unroll
        for (int o = 16; o; o >>= 1) x += __shfl_xor_sync(0xffffffffu, x, o);
        if (lane == 0) red[w*N + i] = x;
    }
    __syncthreads();
    if (threadIdx.x < N){
        float s = 0.f;
        #pragma unroll
        for (int ww = 0; ww < 8; ww++) s += red[ww*N + threadIdx.x];
        out[threadIdx.x] = s;
    }
    __syncthreads();
}

// ---------------- kernel A: prompts P/S + history, build packed consts ----------------
__global__ __launch_bounds__(256)
void k_prompt(const int* uid, const float* Pm, const float* Sm,
              const float* Wk, const float* bk, const float* Wv, const float* bv,
              const float* zg, const float* zb, const float* sg, const float* sb,
              const float* ng, const float* nb,
              const float* pzbuf, const float* psbuf, int LP)
{
    extern __shared__ float sm[];
    float* Wks  = sm;              // 4096
    float* Wvs  = sm + 4096;       // 4096
    float* bufA = sm + 8192;       // 4096  (Ps_ln)
    float* bufB = sm + 12288;      // 4096  (Ss_ln -> pnam scratch)
    float* xr   = sm + 16384;      // 64
    float* zr   = xr + 64;         // 64
    float* vr   = zr + 64;         // 64
    float* zl   = vr + 64;         // 64 (S_z_ln)
    float* red  = zl + 64;         // 64
    float* outr = red + 64;        // 8

    int tid = threadIdx.x, b = blockIdx.x;
    int p = tid & 63, d0 = (tid >> 6) * 16;

    if (b == 0 && tid == 0){ g_acc[0] = 0.0; g_acc[1] = 0.0; }

    for (int i = tid; i < 4096; i += 256){ Wks[i] = Wk[i]; Wvs[i] = Wv[i]; }
    __syncthreads();

    for (int pass = 0; pass < 2; pass++){
        const float* X = pass ? Sm : Pm;
        float acc[16];
        #pragma unroll
        for (int i = 0; i < 16; i++) acc[i] = 0.f;
        float zs = 0.f;

        for (int r = 0; r < LP; r++){
            if (tid < 64) xr[tid] = X[(b*LP + r)*64 + tid];
            __syncthreads();
            if (tid < 64){
                float s = bk[tid];
                #pragma unroll
                for (int k = 0; k < 64; k++) s += xr[k] * Wks[k*64 + tid];
                zr[tid] = eluf(s);
            } else if (tid < 128){
                int t = tid - 64; float s = bv[t];
                #pragma unroll
                for (int k = 0; k < 64; k++) s += xr[k] * Wvs[k*64 + t];
                vr[t] = s;
            }
            __syncthreads();
            float vv = vr[p];
            #pragma unroll
            for (int i = 0; i < 16; i++) acc[i] += zr[d0 + i] * vv;
            if (tid < 64) zs += zr[tid];
            __syncthreads();
        }
        // LN over z (D=64); EPS shift cancels in mean-subtraction
        float rv[2]; rv[0] = (tid < 64) ? zs : 0.f; rv[1] = (tid < 64) ? zs*zs : 0.f;
        block_reduce<2>(rv, red, outr);
        float mz = outr[0] * (1.f/64.f);
        float ivz = rsqrtf(outr[1]*(1.f/64.f) - mz*mz + LN_EPS);
        if (tid < 64){
            float zln = (zs - mz) * ivz * zg[tid] + zb[tid];
            if (pass == 0) g_Pz[b*64 + tid] = zln; else zl[tid] = zln;
        }
        // LN over s (D*D=4096)
        float sv[2] = {0.f, 0.f};
        #pragma unroll
        for (int i = 0; i < 16; i++){ sv[0] += acc[i]; sv[1] += acc[i]*acc[i]; }
        block_reduce<2>(sv, red, outr);
        float ms = outr[0] * (1.f/4096.f);
        float ivs = rsqrtf(outr[1]*(1.f/4096.f) - ms*ms + LN_EPS);
        float* buf = pass ? bufB : bufA;
        #pragma unroll
        for (int i = 0; i < 16; i++){
            int e = (d0 + i)*64 + p;
            buf[e] = (acc[i] - ms) * ivs * sg[e] + sb[e];
        }
        __syncthreads();
    }

    // history path
    int u = uid[b];
    float pzv = 0.f;
    if (tid < 64) pzv = pzbuf[(size_t)u*64 + tid] + zl[tid];
    float rv1[1]; rv1[0] = (tid < 64) ? pzv*pzv : 0.f;
    block_reduce<1>(rv1, red, outr);
    float ipn = 1.f / (fmaxf(sqrtf(outr[0]), 1e-8f) + EPS);

    float pn16[16]; float sv[2] = {0.f, 0.f};
    #pragma unroll
    for (int k2 = 0; k2 < 16; k2++){
        int e = tid + k2*256;
        float pv = (psbuf[(size_t)u*4096 + e] + bufB[e]) * ipn;
        pn16[k2] = pv; sv[0] += pv; sv[1] += pv*pv;
    }
    block_reduce<2>(sv, red, outr);
    float mp = outr[0] * (1.f/4096.f);
    float ivp = rsqrtf(outr[1]*(1.f/4096.f) - mp*mp + LN_EPS);
    #pragma unroll
    for (int k2 = 0; k2 < 16; k2++){
        int e = tid + k2*256;
        float M = (pn16[k2] - mp) * ivp * ng[e] + nb[e];
        g_pack[b*4096 + e] = make_float4(sg[e], sb[e] + bufA[e], ng[e], nb[e] + M);
    }
}

// ---------------- kernel B: q/z/v GEMVs + per-chunk partial sums ----------------
__global__ __launch_bounds__(256)
void k_phase1(const float* X, const float* Wq, const float* bq,
              const float* Wk, const float* bk, const float* Wv, const float* bv,
              int NCH)
{
    extern __shared__ float sm[];
    float* Wqs = sm;             // 4096
    float* Wks = sm + 4096;      // 4096
    float* Wvs = sm + 8192;      // 4096
    float* xr  = sm + 12288;     // 64
    float* zr  = xr + 64;        // 64
    float* vr  = zr + 64;        // 64
    float* qn  = vr + 64;        // 8

    int tid = threadIdx.x;
    int b = blockIdx.x / NCH, ch = blockIdx.x % NCH;
    int p = tid & 63, d0 = (tid >> 6) * 16;
    int L = NCH * CHUNK;

    for (int i = tid; i < 4096; i += 256){ Wqs[i] = Wq[i]; Wks[i] = Wk[i]; Wvs[i] = Wv[i]; }
    __syncthreads();

    float acc[16];
    #pragma unroll
    for (int i = 0; i < 16; i++) acc[i] = 0.f;
    float zs = 0.f;

    for (int r = 0; r < CHUNK; r++){
        int l = ch*CHUNK + r;
        size_t idx = ((size_t)b*L + l) * 64;
        if (tid < 64) xr[tid] = X[idx + tid];
        __syncthreads();
        if (tid < 64){
            float s = bq[tid];
            #pragma unroll
            for (int k = 0; k < 64; k++) s += xr[k] * Wqs[k*64 + tid];
            float qv = eluf(s);
            g_q[idx + tid] = qv;
            float qq = qv*qv;
            #pragma unroll
            for (int o = 16; o; o >>= 1) qq += __shfl_xor_sync(0xffffffffu, qq, o);
            if ((tid & 31) == 0) qn[tid >> 5] = qq;
        } else if (tid < 128){
            int t = tid - 64; float s = bk[t];
            #pragma unroll
            for (int k = 0; k < 64; k++) s += xr[k] * Wks[k*64 + t];
            float zv = eluf(s);
            zr[t] = zv; g_z[idx + t] = zv;
        } else if (tid < 192){
            int t = tid - 128; float s = bv[t];
            #pragma unroll
            for (int k = 0; k < 64; k++) s += xr[k] * Wvs[k*64 + t];
            vr[t] = s; g_v[idx + t] = s;
        }
        __syncthreads();
        if (tid == 0) g_rqn[(size_t)b*L + l] = 1.f / fmaxf(sqrtf(qn[0] + qn[1]), 1e-8f);
        float vv = vr[p];
        #pragma unroll
        for (int i = 0; i < 16; i++) acc[i] += zr[d0 + i] * vv;
        if (tid < 64) zs += zr[tid];
        __syncthreads();
    }
    size_t o = (size_t)(b*NCH + ch) * 4160;
    #pragma unroll
    for (int i = 0; i < 16; i++) g_part[o + (d0 + i)*64 + p] = acc[i];
    if (tid < 64) g_part[o + 4096 + tid] = zs;
}

// ---------------- kernel C: exclusive prefix of chunk partials per batch ----------------
__global__ __launch_bounds__(256)
void k_prefix(int NCH)
{
    int b = blockIdx.x, tid = threadIdx.x;
    float run[17];
    #pragma unroll
    for (int k = 0; k < 17; k++) run[k] = 0.f;
    for (int ch = 0; ch < NCH; ch++){
        size_t o = (size_t)(b*NCH + ch) * 4160;
        #pragma unroll
        for (int k = 0; k < 17; k++){
            int e = tid + k*256;
            if (e < 4160){ g_base[o + e] = run[k]; run[k] += g_part[o + e]; }
        }
    }
}

// ---------------- kernel D: main per-step scan ----------------
__global__ __launch_bounds__(256)
void k_main(const float* zg, const float* zb, const float* nag, const float* nab,
            float* out, int NCH)
{
    extern __shared__ float sm[];
    float4* pk   = (float4*)sm;          // 4096 float4 (16384 floats)
    float* zst   = sm + 16384;           // 64
    float* vst   = zst + 64;             // 64
    float* qst   = vst + 64;             // 64
    float* zpx   = qst + 64;             // 64  z_g
    float* zpy   = zpx + 64;             // 64  z_b + Pz
    float* nagz  = zpy + 64;             // 64
    float* nabz  = nagz + 64;            // 64
    float* na_part = nabz + 64;          // 256
    float* red   = na_part + 256;        // 64
    float* outr  = red + 64;             // 8
    float* srq   = outr + 8;             // 4

    int tid = threadIdx.x;
    int b = blockIdx.x / NCH, ch = blockIdx.x % NCH;
    int p = tid & 63, d0 = (tid >> 6) * 16;
    int L = NCH * CHUNK;

    for (int i = tid; i < 4096; i += 256) pk[i] = g_pack[b*4096 + i];
    if (tid < 64){
        zpx[tid] = zg[tid];
        zpy[tid] = zb[tid] + g_Pz[b*64 + tid];
        nagz[tid] = nag[tid];
        nabz[tid] = nab[tid];
    }
    float A[16];
    size_t ob = (size_t)(b*NCH + ch) * 4160;
    #pragma unroll
    for (int i = 0; i < 16; i++) A[i] = g_base[ob + (d0 + i)*64 + p];
    float zc = (tid < 64) ? g_base[ob + 4096 + tid] : 0.f;
    double dsum = 0.0, dsq = 0.0;
    __syncthreads();

    for (int r = 0; r < CHUNK; r++){
        int l = ch*CHUNK + r;
        size_t idx = ((size_t)b*L + l) * 64;
        if (tid < 64)        zst[tid]      = g_z[idx + tid];
        else if (tid < 128)  vst[tid - 64] = g_v[idx + tid - 64];
        else if (tid < 192)  qst[tid - 128]= g_q[idx + tid - 128];
        else if (tid == 192) srq[0]        = g_rqn[(size_t)b*L + l];
        __syncthreads();

        if (tid < 64) zc += zst[tid];
        float vv = vst[p];
        float rv[4] = {0.f, 0.f, 0.f, 0.f};
        #pragma unroll
        for (int i = 0; i < 16; i++){
            A[i] += zst[d0 + i] * vv;
            rv[0] += A[i]; rv[1] += A[i]*A[i];
        }
        if (tid < 64){ rv[2] = zc; rv[3] = zc*zc; }
        block_reduce<4>(rv, red, outr);
        float aBar = outr[0] * (1.f/4096.f);
        float ivs  = rsqrtf(outr[1]*(1.f/4096.f) - aBar*aBar + LN_EPS);
        float mzv  = outr[2] * (1.f/64.f);
        float ivz  = rsqrtf(outr[3]*(1.f/64.f) - mzv*mzv + LN_EPS);

        float sv[3] = {0.f, 0.f, 0.f};
        float st[16];
        #pragma unroll
        for (int i = 0; i < 16; i++){
            float4 w = pk[(d0 + i)*64 + p];
            float t = (A[i] - aBar) * ivs;
            st[i] = t * w.x + w.y;               // s_ln + Ps
            sv[0] += st[i]; sv[1] += st[i]*st[i];
        }
        if (tid < 64){
            float zt = (zc - mzv) * ivz * zpx[tid] + zpy[tid];   // z_tot
            sv[2] = zt*zt;
            float rr = qst[tid] / fmaxf(zt, 1e-6f);
            dsum += (double)rr; dsq += (double)rr * (double)rr;
        }
        block_reduce<3>(sv, red, outr);
        float zn   = fmaxf(sqrtf(outr[2]), 1e-8f);
        float izn  = 1.f / zn;
        float mst  = outr[0] * (1.f/4096.f);
        float mnam = mst * izn;
        float vnam = (outr[1]*(1.f/4096.f) - mst*mst) * izn * izn;
        float ivn  = rsqrtf(vnam + LN_EPS);
        float k1   = izn * ivn, k0 = -mnam * ivn;

        float accn = 0.f;
        #pragma unroll
        for (int i = 0; i < 16; i++){
            float4 w = pk[(d0 + i)*64 + p];
            float a = st[i] * k1 + k0;
            accn += qst[d0 + i] * (a * w.z + w.w);   // includes +Mprev via w.w
        }
        na_part[tid] = accn;
        __syncthreads();

        float nv = 0.f;
        if (tid < 64){
            nv = (na_part[tid] + na_part[tid+64] + na_part[tid+128] + na_part[tid+192]) * srq[0];
            float s1 = nv, s2 = nv*nv;
            #pragma unroll
            for (int o = 16; o; o >>= 1){
                s1 += __shfl_xor_sync(0xffffffffu, s1, o);
                s2 += __shfl_xor_sync(0xffffffffu, s2, o);
            }
            if ((tid & 31) == 0){ red[(tid>>5)*2] = s1; red[(tid>>5)*2 + 1] = s2; }
        }
        __syncthreads();
        if (tid < 64){
            float S1 = red[0] + red[2], S2 = red[1] + red[3];
            float mn = S1 * (1.f/64.f);
            float iv = rsqrtf(S2*(1.f/64.f) - mn*mn + LN_EPS);
            out[idx + tid] = (nv - mn) * iv * nagz[tid] + nabz[tid];
        }
        __syncthreads();   // protect red/zst/etc. before next iteration
    }

    // reduce local double sums -> global
    __syncthreads();
    double* db = (double*)sm;
    if (tid < 64){ db[tid] = dsum; db[64 + tid] = dsq; }
    __syncthreads();
    if (tid == 0){
        double a = 0.0, c = 0.0;
        for (int i = 0; i < 64; i++){ a += db[i]; c += db[64 + i]; }
        atomicAdd(&g_acc[0], a);
        atomicAdd(&g_acc[1], c);
    }
}

// ---------------- kernel E: finalize std ----------------
__global__ void k_std(float* out, int n, int outpos)
{
    double mean = g_acc[0] / (double)n;
    double var  = (g_acc[1] - g_acc[0]*mean) / (double)(n - 1);
    out[outpos] = (float)sqrt(var);
}

// ---------------- launch ----------------
extern "C" void kernel_launch(void* const* d_in, const int* in_sizes, int n_in,
                              void* d_out, int out_size)
{
    const int*   uid   = (const int*)  d_in[0];
    const float* X     = (const float*)d_in[1];
    const float* Pm    = (const float*)d_in[2];
    const float* Sm    = (const float*)d_in[3];
    const float* Wq    = (const float*)d_in[4];
    const float* bq    = (const float*)d_in[5];
    const float* Wk    = (const float*)d_in[6];
    const float* bk    = (const float*)d_in[7];
    const float* Wv    = (const float*)d_in[8];
    const float* bv    = (const float*)d_in[9];
    const float* zg    = (const float*)d_in[10];
    const float* zb    = (const float*)d_in[11];
    const float* sg    = (const float*)d_in[12];
    const float* sb    = (const float*)d_in[13];
    const float* ng    = (const float*)d_in[14];
    const float* nb    = (const float*)d_in[15];
    const float* nag   = (const float*)d_in[16];
    const float* nab   = (const float*)d_in[17];
    const float* pzbuf = (const float*)d_in[18];
    const float* psbuf = (const float*)d_in[19];
    float* out = (float*)d_out;

    int B   = in_sizes[0];
    int L   = in_sizes[1] / (B * 64);
    int LP  = in_sizes[2] / (B * 64);
    int NCH = L / CHUNK;

    size_t smA = (size_t)(16384 + 64*4 + 64 + 8) * 4;           // ~66.8 KB
    size_t smB = (size_t)(12288 + 64*3 + 8) * 4;                // ~49.9 KB
    size_t smD = (size_t)(16384 + 64*3 + 64*4 + 256 + 64 + 8 + 4) * 4; // ~68.7 KB

    cudaFuncSetAttribute(k_prompt, cudaFuncAttributeMaxDynamicSharedMemorySize, (int)smA);
    cudaFuncSetAttribute(k_phase1, cudaFuncAttributeMaxDynamicSharedMemorySize, (int)smB);
    cudaFuncSetAttribute(k_main,   cudaFuncAttributeMaxDynamicSharedMemorySize, (int)smD);

    k_prompt<<<B, 256, smA>>>(uid, Pm, Sm, Wk, bk, Wv, bv, zg, zb, sg, sb, ng, nb,
                              pzbuf, psbuf, LP);
    k_phase1<<<B*NCH, 256, smB>>>(X, Wq, bq, Wk, bk, Wv, bv, NCH);
    k_prefix<<<B, 256>>>(NCH);
    k_main<<<B*NCH, 256, smD>>>(zg, zb, nag, nab, out, NCH);
    k_std<<<1, 1>>>(out, B*L*64, out_size - 1);
}

// round 2
// speedup vs baseline: 1.0014x; 1.0014x over previous
#include <cuda_runtime.h>
#include <math.h>

#define EPS 1e-8f
#define LN_EPS 1e-5f
#define CHUNK 32

// ---------------- scratch (static __device__, no allocs) ----------------
__device__ float  g_q[16*512*64];
__device__ float  g_z[16*512*64];
__device__ float  g_v[16*512*64];
__device__ float  g_rqn[16*512];
__device__ float  g_part[16*16*4160];
__device__ float  g_base[16*16*4160];
__device__ float4 g_pack[16*4096];      // {sg, sb+Ps_ln, ng, nb+Mprev_ln}
__device__ float  g_Pz[16*64];          // P_z_ln last step per batch
__device__ double g_acc[2];             // sum, sumsq for std

__device__ __forceinline__ float eluf(float x){ return x > 0.f ? x : (expf(x) - 1.f); }

// block of 256 threads (8 warps). red: >= 8*N floats smem, out: >= N floats smem
template<int N>
__device__ __forceinline__ void block_reduce(float* v, float* red, float* out){
    int lane = threadIdx.x & 31, w = threadIdx.x >> 5;
    #pragma unroll
    for (int i = 0; i < N; i++){
        float x = v[i];
        #pragma unroll
        for (int o = 16; o; o >>= 1) x += __shfl_xor_sync(0xffffffffu, x, o);
        if (lane == 0) red[w*N + i] = x;
    }
    __syncthreads();
    if (threadIdx.x < N){
        float s = 0.f;
        #pragma unroll
        for (int ww = 0; ww < 8; ww++) s += red[ww*N + threadIdx.x];
        out[threadIdx.x] = s;
    }
    __syncthreads();
}

// ---------------- kernel A: prompts P/S + history, build packed consts ----------------
__global__ __launch_bounds__(256)
void k_prompt(const int* uid, const float* Pm, const float* Sm,
              const float* Wk, const float* bk, const float* Wv, const float* bv,
              const float* zg, const float* zb, const float* sg, const float* sb,
              const float* ng, const float* nb,
              const float* pzbuf, const float* psbuf, int LP)
{
    extern __shared__ float sm[];
    float* Wks  = sm;              // 4096
    float* Wvs  = sm + 4096;       // 4096
    float* bufA = sm + 8192;       // 4096  (Ps_ln)
    float* bufB = sm + 12288;      // 4096  (Ss_ln -> pnam scratch)
    float* xr   = sm + 16384;      // 64
    float* zr   = xr + 64;         // 64
    float* vr   = zr + 64;         // 64
    float* zl   = vr + 64;         // 64 (S_z_ln)
    float* red  = zl + 64;         // 64
    float* outr = red + 64;        // 8

    int tid = threadIdx.x, b = blockIdx.x;
    int p = tid & 63, d0 = (tid >> 6) * 16;

    if (b == 0 && tid == 0){ g_acc[0] = 0.0; g_acc[1] = 0.0; }

    for (int i = tid; i < 4096; i += 256){ Wks[i] = Wk[i]; Wvs[i] = Wv[i]; }
    __syncthreads();

    for (int pass = 0; pass < 2; pass++){
        const float* X = pass ? Sm : Pm;
        float acc[16];
        #pragma unroll
        for (int i = 0; i < 16; i++) acc[i] = 0.f;
        float zs = 0.f;

        for (int r = 0; r < LP; r++){
            if (tid < 64) xr[tid] = X[(b*LP + r)*64 + tid];
            __syncthreads();
            if (tid < 64){
                float s = bk[tid];
                #pragma unroll
                for (int k = 0; k < 64; k++) s += xr[k] * Wks[k*64 + tid];
                zr[tid] = eluf(s);
            } else if (tid < 128){
                int t = tid - 64; float s = bv[t];
                #pragma unroll
                for (int k = 0; k < 64; k++) s += xr[k] * Wvs[k*64 + t];
                vr[t] = s;
            }
            __syncthreads();
            float vv = vr[p];
            #pragma unroll
            for (int i = 0; i < 16; i++) acc[i] += zr[d0 + i] * vv;
            if (tid < 64) zs += zr[tid];
            __syncthreads();
        }
        // LN over z (D=64); EPS shift cancels in mean-subtraction
        float rv[2]; rv[0] = (tid < 64) ? zs : 0.f; rv[1] = (tid < 64) ? zs*zs : 0.f;
        block_reduce<2>(rv, red, outr);
        float mz = outr[0] * (1.f/64.f);
        float ivz = rsqrtf(outr[1]*(1.f/64.f) - mz*mz + LN_EPS);
        if (tid < 64){
            float zln = (zs - mz) * ivz * zg[tid] + zb[tid];
            if (pass == 0) g_Pz[b*64 + tid] = zln; else zl[tid] = zln;
        }
        // LN over s (D*D=4096)
        float sv[2] = {0.f, 0.f};
        #pragma unroll
        for (int i = 0; i < 16; i++){ sv[0] += acc[i]; sv[1] += acc[i]*acc[i]; }
        block_reduce<2>(sv, red, outr);
        float ms = outr[0] * (1.f/4096.f);
        float ivs = rsqrtf(outr[1]*(1.f/4096.f) - ms*ms + LN_EPS);
        float* buf = pass ? bufB : bufA;
        #pragma unroll
        for (int i = 0; i < 16; i++){
            int e = (d0 + i)*64 + p;
            buf[e] = (acc[i] - ms) * ivs * sg[e] + sb[e];
        }
        __syncthreads();
    }

    // history path
    int u = uid[b];
    float pzv = 0.f;
    if (tid < 64) pzv = pzbuf[(size_t)u*64 + tid] + zl[tid];
    float rv1[1]; rv1[0] = (tid < 64) ? pzv*pzv : 0.f;
    block_reduce<1>(rv1, red, outr);
    float ipn = 1.f / (fmaxf(sqrtf(outr[0]), 1e-8f) + EPS);

    float pn16[16]; float sv[2] = {0.f, 0.f};
    #pragma unroll
    for (int k2 = 0; k2 < 16; k2++){
        int e = tid + k2*256;
        float pv = (psbuf[(size_t)u*4096 + e] + bufB[e]) * ipn;
        pn16[k2] = pv; sv[0] += pv; sv[1] += pv*pv;
    }
    block_reduce<2>(sv, red, outr);
    float mp = outr[0] * (1.f/4096.f);
    float ivp = rsqrtf(outr[1]*(1.f/4096.f) - mp*mp + LN_EPS);
    #pragma unroll
    for (int k2 = 0; k2 < 16; k2++){
        int e = tid + k2*256;
        float M = (pn16[k2] - mp) * ivp * ng[e] + nb[e];
        g_pack[b*4096 + e] = make_float4(sg[e], sb[e] + bufA[e], ng[e], nb[e] + M);
    }
}

// ---------------- kernel B: q/z/v GEMVs + per-chunk partial sums ----------------
__global__ __launch_bounds__(256)
void k_phase1(const float* X, const float* Wq, const float* bq,
              const float* Wk, const float* bk, const float* Wv, const float* bv,
              int NCH)
{
    extern __shared__ float sm[];
    float* Wqs = sm;             // 4096
    float* Wks = sm + 4096;      // 4096
    float* Wvs = sm + 8192;      // 4096
    float* xr  = sm + 12288;     // 64
    float* zr  = xr + 64;        // 64
    float* vr  = zr + 64;        // 64
    float* qn  = vr + 64;        // 8

    int tid = threadIdx.x;
    int b = blockIdx.x / NCH, ch = blockIdx.x % NCH;
    int p = tid & 63, d0 = (tid >> 6) * 16;
    int L = NCH * CHUNK;

    for (int i = tid; i < 4096; i += 256){ Wqs[i] = Wq[i]; Wks[i] = Wk[i]; Wvs[i] = Wv[i]; }
    __syncthreads();

    float acc[16];
    #pragma unroll
    for (int i = 0; i < 16; i++) acc[i] = 0.f;
    float zs = 0.f;

    for (int r = 0; r < CHUNK; r++){
        int l = ch*CHUNK + r;
        size_t idx = ((size_t)b*L + l) * 64;
        if (tid < 64) xr[tid] = X[idx + tid];
        __syncthreads();
        if (tid < 64){
            float s = bq[tid];
            #pragma unroll
            for (int k = 0; k < 64; k++) s += xr[k] * Wqs[k*64 + tid];
            float qv = eluf(s);
            g_q[idx + tid] = qv;
            float qq = qv*qv;
            #pragma unroll
            for (int o = 16; o; o >>= 1) qq += __shfl_xor_sync(0xffffffffu, qq, o);
            if ((tid & 31) == 0) qn[tid >> 5] = qq;
        } else if (tid < 128){
            int t = tid - 64; float s = bk[t];
            #pragma unroll
            for (int k = 0; k < 64; k++) s += xr[k] * Wks[k*64 + t];
            float zv = eluf(s);
            zr[t] = zv; g_z[idx + t] = zv;
        } else if (tid < 192){
            int t = tid - 128; float s = bv[t];
            #pragma unroll
            for (int k = 0; k < 64; k++) s += xr[k] * Wvs[k*64 + t];
            vr[t] = s; g_v[idx + t] = s;
        }
        __syncthreads();
        if (tid == 0) g_rqn[(size_t)b*L + l] = 1.f / fmaxf(sqrtf(qn[0] + qn[1]), 1e-8f);
        float vv = vr[p];
        #pragma unroll
        for (int i = 0; i < 16; i++) acc[i] += zr[d0 + i] * vv;
        if (tid < 64) zs += zr[tid];
        __syncthreads();
    }
    size_t o = (size_t)(b*NCH + ch) * 4160;
    #pragma unroll
    for (int i = 0; i < 16; i++) g_part[o + (d0 + i)*64 + p] = acc[i];
    if (tid < 64) g_part[o + 4096 + tid] = zs;
}

// ---------------- kernel C: exclusive prefix of chunk partials per batch ----------------
__global__ __launch_bounds__(256)
void k_prefix(int NCH)
{
    int b = blockIdx.x, tid = threadIdx.x;
    float run[17];
    #pragma unroll
    for (int k = 0; k < 17; k++) run[k] = 0.f;
    for (int ch = 0; ch < NCH; ch++){
        size_t o = (size_t)(b*NCH + ch) * 4160;
        #pragma unroll
        for (int k = 0; k < 17; k++){
            int e = tid + k*256;
            if (e < 4160){ g_base[o + e] = run[k]; run[k] += g_part[o + e]; }
        }
    }
}

// ---------------- kernel D: main per-step scan ----------------
__global__ __launch_bounds__(256)
void k_main(const float* zg, const float* zb, const float* nag, const float* nab,
            float* out, int NCH)
{
    extern __shared__ float sm[];
    float4* pk   = (float4*)sm;          // 4096 float4 (16384 floats)
    float* zst   = sm + 16384;           // 64
    float* vst   = zst + 64;             // 64
    float* qst   = vst + 64;             // 64
    float* zpx   = qst + 64;             // 64  z_g
    float* zpy   = zpx + 64;             // 64  z_b + Pz
    float* nagz  = zpy + 64;             // 64
    float* nabz  = nagz + 64;            // 64
    float* na_part = nabz + 64;          // 256
    float* red   = na_part + 256;        // 64
    float* outr  = red + 64;             // 8
    float* srq   = outr + 8;             // 4

    int tid = threadIdx.x;
    int b = blockIdx.x / NCH, ch = blockIdx.x % NCH;
    int p = tid & 63, d0 = (tid >> 6) * 16;
    int L = NCH * CHUNK;

    for (int i = tid; i < 4096; i += 256) pk[i] = g_pack[b*4096 + i];
    if (tid < 64){
        zpx[tid] = zg[tid];
        zpy[tid] = zb[tid] + g_Pz[b*64 + tid];
        nagz[tid] = nag[tid];
        nabz[tid] = nab[tid];
    }
    float A[16];
    size_t ob = (size_t)(b*NCH + ch) * 4160;
    #pragma unroll
    for (int i = 0; i < 16; i++) A[i] = g_base[ob + (d0 + i)*64 + p];
    float zc = (tid < 64) ? g_base[ob + 4096 + tid] : 0.f;
    double dsum = 0.0, dsq = 0.0;
    __syncthreads();

    for (int r = 0; r < CHUNK; r++){
        int l = ch*CHUNK + r;
        size_t idx = ((size_t)b*L + l) * 64;
        if (tid < 64)        zst[tid]      = g_z[idx + tid];
        else if (tid < 128)  vst[tid - 64] = g_v[idx + tid - 64];
        else if (tid < 192)  qst[tid - 128]= g_q[idx + tid - 128];
        else if (tid == 192) srq[0]        = g_rqn[(size_t)b*L + l];
        __syncthreads();

        if (tid < 64) zc += zst[tid];
        float vv = vst[p];
        float rv[4] = {0.f, 0.f, 0.f, 0.f};
        #pragma unroll
        for (int i = 0; i < 16; i++){
            A[i] += zst[d0 + i] * vv;
            rv[0] += A[i]; rv[1] += A[i]*A[i];
        }
        if (tid < 64){ rv[2] = zc; rv[3] = zc*zc; }
        block_reduce<4>(rv, red, outr);
        float aBar = outr[0] * (1.f/4096.f);
        float ivs  = rsqrtf(outr[1]*(1.f/4096.f) - aBar*aBar + LN_EPS);
        float mzv  = outr[2] * (1.f/64.f);
        float ivz  = rsqrtf(outr[3]*(1.f/64.f) - mzv*mzv + LN_EPS);

        float sv[3] = {0.f, 0.f, 0.f};
        float st[16];
        #pragma unroll
        for (int i = 0; i < 16; i++){
            float4 w = pk[(d0 + i)*64 + p];
            float t = (A[i] - aBar) * ivs;
            st[i] = t * w.x + w.y;               // s_ln + Ps
            sv[0] += st[i]; sv[1] += st[i]*st[i];
        }
        if (tid < 64){
            float zt = (zc - mzv) * ivz * zpx[tid] + zpy[tid];   // z_tot
            sv[2] = zt*zt;
            float rr = qst[tid] / fmaxf(zt, 1e-6f);
            dsum += (double)rr; dsq += (double)rr * (double)rr;
        }
        block_reduce<3>(sv, red, outr);
        float zn   = fmaxf(sqrtf(outr[2]), 1e-8f);
        float izn  = 1.f / zn;
        float mst  = outr[0] * (1.f/4096.f);
        float mnam = mst * izn;
        float vnam = (outr[1]*(1.f/4096.f) - mst*mst) * izn * izn;
        float ivn  = rsqrtf(vnam + LN_EPS);
        float k1   = izn * ivn, k0 = -mnam * ivn;

        float accn = 0.f;
        #pragma unroll
        for (int i = 0; i < 16; i++){
            float4 w = pk[(d0 + i)*64 + p];
            float a = st[i] * k1 + k0;
            accn += qst[d0 + i] * (a * w.z + w.w);   // includes +Mprev via w.w
        }
        na_part[tid] = accn;
        __syncthreads();

        float nv = 0.f;
        if (tid < 64){
            nv = (na_part[tid] + na_part[tid+64] + na_part[tid+128] + na_part[tid+192]) * srq[0];
            float s1 = nv, s2 = nv*nv;
            #pragma unroll
            for (int o = 16; o; o >>= 1){
                s1 += __shfl_xor_sync(0xffffffffu, s1, o);
                s2 += __shfl_xor_sync(0xffffffffu, s2, o);
            }
            if ((tid & 31) == 0){ red[(tid>>5)*2] = s1; red[(tid>>5)*2 + 1] = s2; }
        }
        __syncthreads();
        if (tid < 64){
            float S1 = red[0] + red[2], S2 = red[1] + red[3];
            float mn = S1 * (1.f/64.f);
            float iv = rsqrtf(S2*(1.f/64.f) - mn*mn + LN_EPS);
            out[idx + tid] = (nv - mn) * iv * nagz[tid] + nabz[tid];
        }
        __syncthreads();   // protect red/zst/etc. before next iteration
    }

    // reduce local double sums -> global
    __syncthreads();
    double* db = (double*)sm;
    if (tid < 64){ db[tid] = dsum; db[64 + tid] = dsq; }
    __syncthreads();
    if (tid == 0){
        double a = 0.0, c = 0.0;
        for (int i = 0; i < 64; i++){ a += db[i]; c += db[64 + i]; }
        atomicAdd(&g_acc[0], a);
        atomicAdd(&g_acc[1], c);
    }
}

// ---------------- kernel E: finalize std ----------------
__global__ void k_std(float* out, int n, int outpos)
{
    double mean = g_acc[0] / (double)n;
    double var  = (g_acc[1] - g_acc[0]*mean) / (double)(n - 1);
    out[outpos] = (float)sqrt(var);
}

// ---------------- launch ----------------
extern "C" void kernel_launch(void* const* d_in, const int* in_sizes, int n_in,
                              void* d_out, int out_size)
{
    const int*   uid   = (const int*)  d_in[0];
    const float* X     = (const float*)d_in[1];
    const float* Pm    = (const float*)d_in[2];
    const float* Sm    = (const float*)d_in[3];
    const float* Wq    = (const float*)d_in[4];
    const float* bq    = (const float*)d_in[5];
    const float* Wk    = (const float*)d_in[6];
    const float* bk    = (const float*)d_in[7];
    const float* Wv    = (const float*)d_in[8];
    const float* bv    = (const float*)d_in[9];
    const float* zg    = (const float*)d_in[10];
    const float* zb    = (const float*)d_in[11];
    const float* sg    = (const float*)d_in[12];
    const float* sb    = (const float*)d_in[13];
    const float* ng    = (const float*)d_in[14];
    const float* nb    = (const float*)d_in[15];
    const float* nag   = (const float*)d_in[16];
    const float* nab   = (const float*)d_in[17];
    const float* pzbuf = (const float*)d_in[18];
    const float* psbuf = (const float*)d_in[19];
    float* out = (float*)d_out;

    int B   = in_sizes[0];
    int L   = in_sizes[1] / (B * 64);
    int LP  = in_sizes[2] / (B * 64);
    int NCH = L / CHUNK;

    size_t smA = (size_t)(16384 + 64*4 + 64 + 8) * 4;           // ~66.8 KB
    size_t smB = (size_t)(12288 + 64*3 + 8) * 4;                // ~49.9 KB
    size_t smD = (size_t)(16384 + 64*3 + 64*4 + 256 + 64 + 8 + 4) * 4; // ~68.7 KB

    cudaFuncSetAttribute(k_prompt, cudaFuncAttributeMaxDynamicSharedMemorySize, (int)smA);
    cudaFuncSetAttribute(k_phase1, cudaFuncAttributeMaxDynamicSharedMemorySize, (int)smB);
    cudaFuncSetAttribute(k_main,   cudaFuncAttributeMaxDynamicSharedMemorySize, (int)smD);

    k_prompt<<<B, 256, smA>>>(uid, Pm, Sm, Wk, bk, Wv, bv, zg, zb, sg, sb, ng, nb,
                              pzbuf, psbuf, LP);
    k_phase1<<<B*NCH, 256, smB>>>(X, Wq, bq, Wk, bk, Wv, bv, NCH);
    k_prefix<<<B, 256>>>(NCH);
    k_main<<<B*NCH, 256, smD>>>(zg, zb, nag, nab, out, NCH);
    k_std<<<1, 1>>>(out, B*L*64, out_size - 1);
}